// round 1
// baseline (speedup 1.0000x reference)
#include <cuda_runtime.h>

// Problem constants
#define BB 2048
#define SS 200
#define DD 64
#define NH1 64
#define NH2 16
#define TS 32          // S-tile
#define EPSV 1e-9f

struct alignas(16) Smem {
    float W1k[64][64];    // W1[k-block] - W1[(q-k)-block]
    float W1qk[64][64];   // W1[q*k block]
    float W2s[64][16];
    float W3s[16];
    float Q[64];
    float Qbias[64];      // q @ (W1[q] + W1[q-k])
    float a1[64], m1[64], r1[64];
    float a2[16], m2[16], r2[16];
    float K[TS][68];      // padded: stride 68 kills 4-way conflicts on column reads
    float Hh1[TS][68];
    float Hh2[TS][16];
    float Score[TS];
    float Red[256];
};

__device__ __forceinline__ float fast_sigmoid(float x) {
    return __fdividef(1.0f, 1.0f + __expf(-x));
}

__global__ void __launch_bounds__(256) din_pool_kernel(
    const float* __restrict__ q_emb,   // (B, 64)
    const float* __restrict__ k_emb,   // (B, S, 64)
    const int*   __restrict__ seqlen,  // (B, 1)
    const float* __restrict__ W1,      // (256, 64)
    const float* __restrict__ alpha1,
    const float* __restrict__ mean1,
    const float* __restrict__ var1,
    const float* __restrict__ W2,      // (64, 16)
    const float* __restrict__ alpha2,
    const float* __restrict__ mean2,
    const float* __restrict__ var2,
    const float* __restrict__ W3,      // (16, 1)
    float* __restrict__ out)           // (B, 64)
{
    extern __shared__ char smem_raw[];
    Smem& sm = *reinterpret_cast<Smem*>(smem_raw);

    const int tid = threadIdx.x;
    const int b   = blockIdx.x;

    // ---- Stage weights + params into smem, with W1 factorization ----
    for (int i = tid; i < 64 * 64; i += 256) {
        int d = i >> 6, h = i & 63;
        float wk  = W1[(64  + d) * 64 + h];
        float wqk = W1[(128 + d) * 64 + h];
        sm.W1k[d][h]  = wk - wqk;
        sm.W1qk[d][h] = W1[(192 + d) * 64 + h];
    }
    for (int i = tid; i < 64 * 16; i += 256)
        sm.W2s[i >> 4][i & 15] = W2[i];
    if (tid < 16) {
        sm.W3s[tid] = W3[tid];
        sm.a2[tid]  = alpha2[tid];
        sm.m2[tid]  = mean2[tid];
        sm.r2[tid]  = rsqrtf(var2[tid] + EPSV);
    }
    if (tid < 64) {
        sm.Q[tid]  = q_emb[b * 64 + tid];
        sm.a1[tid] = alpha1[tid];
        sm.m1[tid] = mean1[tid];
        sm.r1[tid] = rsqrtf(var1[tid] + EPSV);
    }
    __syncthreads();

    // ---- Per-batch q bias: q @ (W1[q-block] + W1[(q-k)-block]) ----
    if (tid < 64) {
        float acc = 0.0f;
        #pragma unroll 8
        for (int d = 0; d < 64; d++)
            acc = fmaf(sm.Q[d], W1[d * 64 + tid] + W1[(128 + d) * 64 + tid], acc);
        sm.Qbias[tid] = acc;
    }

    const int L = seqlen[b];

    // stage-1 thread mapping: 8 col-groups x 32 rows
    const int c  = tid & 7;
    const int r  = tid >> 3;
    const int c8 = c * 8;
    // epilogue mapping
    const int ed = tid & 63;
    const int er = tid >> 6;
    float po = 0.0f;     // partial of out[b][ed]

    for (int s0 = 0; s0 < L; s0 += TS) {
        // ---- load K tile (float4, coalesced) ----
        for (int i = tid; i < TS * 16; i += 256) {
            int s  = i >> 4;
            int dd = (i & 15) * 4;
            int gs = s0 + s;
            float4 v = make_float4(0.f, 0.f, 0.f, 0.f);
            if (gs < SS)
                v = *reinterpret_cast<const float4*>(&k_emb[((long)b * SS + gs) * 64 + dd]);
            *reinterpret_cast<float4*>(&sm.K[s][dd]) = v;
        }
        __syncthreads();

        // ---- stage 1: H1[r][c8..c8+7] = Qbias + k@W1k + (q*k)@W1qk ----
        float acc[8];
        #pragma unroll
        for (int j = 0; j < 8; j++) acc[j] = sm.Qbias[c8 + j];

        #pragma unroll 8
        for (int d = 0; d < 64; d++) {
            float kv = sm.K[r][d];
            float kq = kv * sm.Q[d];
            float4 w0 = *reinterpret_cast<const float4*>(&sm.W1k[d][c8]);
            float4 w1 = *reinterpret_cast<const float4*>(&sm.W1k[d][c8 + 4]);
            float4 u0 = *reinterpret_cast<const float4*>(&sm.W1qk[d][c8]);
            float4 u1 = *reinterpret_cast<const float4*>(&sm.W1qk[d][c8 + 4]);
            acc[0] = fmaf(kv, w0.x, acc[0]); acc[0] = fmaf(kq, u0.x, acc[0]);
            acc[1] = fmaf(kv, w0.y, acc[1]); acc[1] = fmaf(kq, u0.y, acc[1]);
            acc[2] = fmaf(kv, w0.z, acc[2]); acc[2] = fmaf(kq, u0.z, acc[2]);
            acc[3] = fmaf(kv, w0.w, acc[3]); acc[3] = fmaf(kq, u0.w, acc[3]);
            acc[4] = fmaf(kv, w1.x, acc[4]); acc[4] = fmaf(kq, u1.x, acc[4]);
            acc[5] = fmaf(kv, w1.y, acc[5]); acc[5] = fmaf(kq, u1.y, acc[5]);
            acc[6] = fmaf(kv, w1.z, acc[6]); acc[6] = fmaf(kq, u1.z, acc[6]);
            acc[7] = fmaf(kv, w1.w, acc[7]); acc[7] = fmaf(kq, u1.w, acc[7]);
        }

        // Dice 1 + write to smem
        #pragma unroll
        for (int j = 0; j < 8; j++) {
            int h = c8 + j;
            float x  = acc[j];
            float xn = (x - sm.m1[h]) * sm.r1[h];
            float p  = fast_sigmoid(xn);
            float a  = sm.a1[h];
            sm.Hh1[r][h] = x * (a + p * (1.0f - a));
        }
        __syncthreads();

        // ---- stage 2: H2[r][c], H2[r][c+8] ----
        float b0 = 0.0f, b1 = 0.0f;
        #pragma unroll 8
        for (int h = 0; h < 64; h++) {
            float hv = sm.Hh1[r][h];
            b0 = fmaf(hv, sm.W2s[h][c],     b0);
            b1 = fmaf(hv, sm.W2s[h][c + 8], b1);
        }
        {
            int j = c;
            float xn = (b0 - sm.m2[j]) * sm.r2[j];
            float p  = fast_sigmoid(xn);
            float a  = sm.a2[j];
            sm.Hh2[r][j] = b0 * (a + p * (1.0f - a));
            j = c + 8;
            xn = (b1 - sm.m2[j]) * sm.r2[j];
            p  = fast_sigmoid(xn);
            a  = sm.a2[j];
            sm.Hh2[r][j] = b1 * (a + p * (1.0f - a));
        }
        __syncthreads();

        // ---- score + mask + sigmoid ----
        if (tid < TS) {
            float sc = 0.0f;
            #pragma unroll
            for (int j = 0; j < 16; j++)
                sc = fmaf(sm.Hh2[tid][j], sm.W3s[j], sc);
            int gs = s0 + tid;
            sm.Score[tid] = (gs < L) ? fast_sigmoid(sc) : 0.0f;
        }
        __syncthreads();

        // ---- epilogue: out[ed] += sum_s score[s] * K[s][ed] ----
        #pragma unroll
        for (int i = 0; i < 8; i++) {
            int s = er * 8 + i;
            po = fmaf(sm.Score[s], sm.K[s][ed], po);
        }
        __syncthreads();   // protect K/Score before next tile overwrites
    }

    // ---- cross-group reduce + store ----
    sm.Red[tid] = po;
    __syncthreads();
    if (tid < 64)
        out[b * 64 + tid] = sm.Red[tid] + sm.Red[64 + tid] + sm.Red[128 + tid] + sm.Red[192 + tid];
}

extern "C" void kernel_launch(void* const* d_in, const int* in_sizes, int n_in,
                              void* d_out, int out_size) {
    const float* q      = (const float*)d_in[0];
    const float* k      = (const float*)d_in[1];
    const int*   sl     = (const int*)  d_in[2];
    const float* W1     = (const float*)d_in[3];
    const float* alpha1 = (const float*)d_in[4];
    const float* mean1  = (const float*)d_in[5];
    const float* var1   = (const float*)d_in[6];
    const float* W2     = (const float*)d_in[7];
    const float* alpha2 = (const float*)d_in[8];
    const float* mean2  = (const float*)d_in[9];
    const float* var2   = (const float*)d_in[10];
    const float* W3     = (const float*)d_in[11];
    float* out = (float*)d_out;

    cudaFuncSetAttribute(din_pool_kernel,
                         cudaFuncAttributeMaxDynamicSharedMemorySize,
                         (int)sizeof(Smem));
    din_pool_kernel<<<BB, 256, sizeof(Smem)>>>(
        q, k, sl, W1, alpha1, mean1, var1, W2, alpha2, mean2, var2, W3, out);
}

// round 2
// speedup vs baseline: 2.6840x; 2.6840x over previous
#include <cuda_runtime.h>

#define BB 2048
#define SS 200
#define TS 64
#define EPSV 1e-9f

struct alignas(16) Smem {
    float W1k[64][64];    // W1[k] - W1[q*k-block coupling]  (see factorization)
    float W1qk[64][64];   // W1[q*k block]
    float W2s[64][16];
    float K[TS][68];      // stride 68: float4-storable, conflict-free col reads
    float Hh1[TS][65];    // stride 65: conflict-free row-major stage-2 reads
    float Spart[4][TS];
    float Score[TS];
    float Red[256];
    float Q[64];
    float Qbias[64];
    float a1[64], m1[64], r1[64];
    float a2[16], m2[16], r2[16];
    float W3s[16];
};

__device__ __forceinline__ float fast_sigmoid(float x) {
    return __fdividef(1.0f, 1.0f + __expf(-x));
}

__global__ void __launch_bounds__(256) din_pool_kernel(
    const float* __restrict__ q_emb,
    const float* __restrict__ k_emb,
    const int*   __restrict__ seqlen,
    const float* __restrict__ W1,
    const float* __restrict__ alpha1,
    const float* __restrict__ mean1,
    const float* __restrict__ var1,
    const float* __restrict__ W2,
    const float* __restrict__ alpha2,
    const float* __restrict__ mean2,
    const float* __restrict__ var2,
    const float* __restrict__ W3,
    float* __restrict__ out)
{
    extern __shared__ char smem_raw[];
    Smem& sm = *reinterpret_cast<Smem*>(smem_raw);

    const int tid = threadIdx.x;
    const int b   = blockIdx.x;

    // ---- Stage weights/params, with W1 concat factorization:
    // [q,k,q-k,q*k]@W1 = q@(W1a+W1c) [bias] + k@(W1b-W1c) + (q*k)@W1d
    for (int i = tid; i < 64 * 64; i += 256) {
        int d = i >> 6, h = i & 63;
        sm.W1k[d][h]  = W1[(64 + d) * 64 + h] - W1[(128 + d) * 64 + h];
        sm.W1qk[d][h] = W1[(192 + d) * 64 + h];
    }
    for (int i = tid; i < 64 * 16; i += 256)
        sm.W2s[i >> 4][i & 15] = W2[i];
    if (tid < 16) {
        sm.W3s[tid] = W3[tid];
        sm.a2[tid]  = alpha2[tid];
        sm.m2[tid]  = mean2[tid];
        sm.r2[tid]  = rsqrtf(var2[tid] + EPSV);
    }
    if (tid < 64) {
        sm.Q[tid]  = q_emb[b * 64 + tid];
        sm.a1[tid] = alpha1[tid];
        sm.m1[tid] = mean1[tid];
        sm.r1[tid] = rsqrtf(var1[tid] + EPSV);
    }
    __syncthreads();

    // Per-batch bias: q @ (W1[q-block] + W1[(q-k)-block])
    if (tid < 64) {
        float acc = 0.0f;
        #pragma unroll 8
        for (int d = 0; d < 64; d++)
            acc = fmaf(sm.Q[d], W1[d * 64 + tid] + W1[(128 + d) * 64 + tid], acc);
        sm.Qbias[tid] = acc;
    }

    const int L = seqlen[b];

    // stage-1 mapping: 2 rows x 8 cols per thread, cols split {4c, 32+4c}
    const int c  = tid & 7;
    const int rr = tid >> 3;           // 0..31 ; rows rr and rr+32
    const int j0 = 4 * c;
    const int j1 = 32 + 4 * c;
    // stage-2 mapping
    const int s2r  = tid & 63;
    const int s2g  = tid >> 6;         // 0..3
    const int s2c4 = s2g * 4;
    // epilogue mapping
    const int ed = tid & 63;
    const int er = tid >> 6;
    float po = 0.0f;

    for (int s0 = 0; s0 < L; s0 += TS) {
        // ---- K tile load (float4, coalesced) ----
        for (int i = tid; i < TS * 16; i += 256) {
            int s  = i >> 4;
            int dd = (i & 15) * 4;
            int gs = s0 + s;
            float4 v = make_float4(0.f, 0.f, 0.f, 0.f);
            if (gs < SS)
                v = *reinterpret_cast<const float4*>(&k_emb[((long)b * SS + gs) * 64 + dd]);
            *reinterpret_cast<float4*>(&sm.K[s][dd]) = v;
        }
        __syncthreads();

        // ---- stage 1 ----
        float acc0[8], acc1[8];
        {
            float4 q0 = *reinterpret_cast<const float4*>(&sm.Qbias[j0]);
            float4 q1 = *reinterpret_cast<const float4*>(&sm.Qbias[j1]);
            acc0[0]=q0.x; acc0[1]=q0.y; acc0[2]=q0.z; acc0[3]=q0.w;
            acc0[4]=q1.x; acc0[5]=q1.y; acc0[6]=q1.z; acc0[7]=q1.w;
            #pragma unroll
            for (int j = 0; j < 8; j++) acc1[j] = acc0[j];
        }

        #pragma unroll 8
        for (int d = 0; d < 64; d++) {
            float kv0 = sm.K[rr][d];
            float kv1 = sm.K[rr + 32][d];
            float qd  = sm.Q[d];
            float kq0 = kv0 * qd;
            float kq1 = kv1 * qd;
            float4 wA = *reinterpret_cast<const float4*>(&sm.W1k[d][j0]);
            float4 wB = *reinterpret_cast<const float4*>(&sm.W1k[d][j1]);
            float4 uA = *reinterpret_cast<const float4*>(&sm.W1qk[d][j0]);
            float4 uB = *reinterpret_cast<const float4*>(&sm.W1qk[d][j1]);
            acc0[0]=fmaf(kv0,wA.x,acc0[0]); acc0[0]=fmaf(kq0,uA.x,acc0[0]);
            acc0[1]=fmaf(kv0,wA.y,acc0[1]); acc0[1]=fmaf(kq0,uA.y,acc0[1]);
            acc0[2]=fmaf(kv0,wA.z,acc0[2]); acc0[2]=fmaf(kq0,uA.z,acc0[2]);
            acc0[3]=fmaf(kv0,wA.w,acc0[3]); acc0[3]=fmaf(kq0,uA.w,acc0[3]);
            acc0[4]=fmaf(kv0,wB.x,acc0[4]); acc0[4]=fmaf(kq0,uB.x,acc0[4]);
            acc0[5]=fmaf(kv0,wB.y,acc0[5]); acc0[5]=fmaf(kq0,uB.y,acc0[5]);
            acc0[6]=fmaf(kv0,wB.z,acc0[6]); acc0[6]=fmaf(kq0,uB.z,acc0[6]);
            acc0[7]=fmaf(kv0,wB.w,acc0[7]); acc0[7]=fmaf(kq0,uB.w,acc0[7]);
            acc1[0]=fmaf(kv1,wA.x,acc1[0]); acc1[0]=fmaf(kq1,uA.x,acc1[0]);
            acc1[1]=fmaf(kv1,wA.y,acc1[1]); acc1[1]=fmaf(kq1,uA.y,acc1[1]);
            acc1[2]=fmaf(kv1,wA.z,acc1[2]); acc1[2]=fmaf(kq1,uA.z,acc1[2]);
            acc1[3]=fmaf(kv1,wA.w,acc1[3]); acc1[3]=fmaf(kq1,uA.w,acc1[3]);
            acc1[4]=fmaf(kv1,wB.x,acc1[4]); acc1[4]=fmaf(kq1,uB.x,acc1[4]);
            acc1[5]=fmaf(kv1,wB.y,acc1[5]); acc1[5]=fmaf(kq1,uB.y,acc1[5]);
            acc1[6]=fmaf(kv1,wB.z,acc1[6]); acc1[6]=fmaf(kq1,uB.z,acc1[6]);
            acc1[7]=fmaf(kv1,wB.w,acc1[7]); acc1[7]=fmaf(kq1,uB.w,acc1[7]);
        }

        // Dice 1 -> Hh1 (both rows)
        #pragma unroll
        for (int j = 0; j < 8; j++) {
            int h = (j < 4) ? (j0 + j) : (j1 + j - 4);
            float m = sm.m1[h], rv = sm.r1[h], a = sm.a1[h];
            float x0 = acc0[j];
            float p0 = fast_sigmoid((x0 - m) * rv);
            sm.Hh1[rr][h] = x0 * (a + p0 * (1.0f - a));
            float x1 = acc1[j];
            float p1 = fast_sigmoid((x1 - m) * rv);
            sm.Hh1[rr + 32][h] = x1 * (a + p1 * (1.0f - a));
        }
        __syncthreads();

        // ---- stage 2: each thread: row s2r, cols s2c4..s2c4+3 ----
        float bacc[4] = {0.f, 0.f, 0.f, 0.f};
        #pragma unroll 8
        for (int h = 0; h < 64; h++) {
            float hv = sm.Hh1[s2r][h];
            float4 w = *reinterpret_cast<const float4*>(&sm.W2s[h][s2c4]);
            bacc[0] = fmaf(hv, w.x, bacc[0]);
            bacc[1] = fmaf(hv, w.y, bacc[1]);
            bacc[2] = fmaf(hv, w.z, bacc[2]);
            bacc[3] = fmaf(hv, w.w, bacc[3]);
        }
        // Dice 2 + W3 partial dot
        float part = 0.0f;
        #pragma unroll
        for (int j = 0; j < 4; j++) {
            int col = s2c4 + j;
            float x  = bacc[j];
            float p  = fast_sigmoid((x - sm.m2[col]) * sm.r2[col]);
            float a  = sm.a2[col];
            part = fmaf(x * (a + p * (1.0f - a)), sm.W3s[col], part);
        }
        sm.Spart[s2g][s2r] = part;
        __syncthreads();

        // ---- score + mask + sigmoid ----
        if (tid < TS) {
            float sc = sm.Spart[0][tid] + sm.Spart[1][tid]
                     + sm.Spart[2][tid] + sm.Spart[3][tid];
            int gs = s0 + tid;
            sm.Score[tid] = (gs < L) ? fast_sigmoid(sc) : 0.0f;
        }
        __syncthreads();

        // ---- epilogue: out[ed] += sum_s score[s] * K[s][ed] ----
        #pragma unroll
        for (int i = 0; i < 16; i++) {
            int s = er * 16 + i;
            po = fmaf(sm.Score[s], sm.K[s][ed], po);
        }
        __syncthreads();
    }

    sm.Red[tid] = po;
    __syncthreads();
    if (tid < 64)
        out[b * 64 + tid] = sm.Red[tid] + sm.Red[64 + tid]
                          + sm.Red[128 + tid] + sm.Red[192 + tid];
}

extern "C" void kernel_launch(void* const* d_in, const int* in_sizes, int n_in,
                              void* d_out, int out_size) {
    const float* q      = (const float*)d_in[0];
    const float* k      = (const float*)d_in[1];
    const int*   sl     = (const int*)  d_in[2];
    const float* W1     = (const float*)d_in[3];
    const float* alpha1 = (const float*)d_in[4];
    const float* mean1  = (const float*)d_in[5];
    const float* var1   = (const float*)d_in[6];
    const float* W2     = (const float*)d_in[7];
    const float* alpha2 = (const float*)d_in[8];
    const float* mean2  = (const float*)d_in[9];
    const float* var2   = (const float*)d_in[10];
    const float* W3     = (const float*)d_in[11];
    float* out = (float*)d_out;

    cudaFuncSetAttribute(din_pool_kernel,
                         cudaFuncAttributeMaxDynamicSharedMemorySize,
                         (int)sizeof(Smem));
    din_pool_kernel<<<BB, 256, sizeof(Smem)>>>(
        q, k, sl, W1, alpha1, mean1, var1, W2, alpha2, mean2, var2, W3, out);
}

// round 3
// speedup vs baseline: 4.5647x; 1.7007x over previous
#include <cuda_runtime.h>
#include <cuda_bf16.h>
#include <cstdint>

#define BB 2048
#define SS 200
#define TS 64
#define EPSV 1e-9f

// A tile: 64 rows x 128 cols (cols 0-63 = k, 64-127 = k*q), bf16 hi/lo
// row stride 136 bf16 = 272B: 16B-aligned rows, granule stride 17 % 8 == 1 -> conflict-free ldmatrix
#define ASTRIDE 136
// H1: 64 x 64 bf16 hi/lo, stride 72 bf16 = 144B (16B aligned, granule stride 9)
#define HSTRIDE 72

struct alignas(16) Smem {
    union {
        struct {
            float W1k[64][64];    // W1[k-block] - W1[(q-k)-block]
            float W1qk[64][64];   // W1[q*k-block]
            float W2s[64][16];
        } w;                      // init only
        struct {
            __nv_bfloat16 Ahi[64][ASTRIDE];
            __nv_bfloat16 Alo[64][ASTRIDE];
        } a;                      // main loop
    } u;
    float K[64][68];
    __nv_bfloat16 H1hi[64][HSTRIDE];
    __nv_bfloat16 H1lo[64][HSTRIDE];
    float Spart[8][64];
    float Score[64];
    float Red[256];
    float Q[64];
    float Qbias[64];
    float a1[64], m1[64], r1[64];
    float a2[16], m2[16], r2[16];
    float W3s[16];
};

__device__ __forceinline__ float fast_sigmoid(float x) {
    return __fdividef(1.0f, 1.0f + __expf(-x));
}
__device__ __forceinline__ uint32_t sptr(const void* p) {
    return (uint32_t)__cvta_generic_to_shared(p);
}
__device__ __forceinline__ void ldsm4(uint32_t r[4], uint32_t addr) {
    asm volatile("ldmatrix.sync.aligned.m8n8.x4.shared.b16 {%0,%1,%2,%3}, [%4];"
                 : "=r"(r[0]), "=r"(r[1]), "=r"(r[2]), "=r"(r[3]) : "r"(addr));
}
__device__ __forceinline__ void mma16816(float c[4], const uint32_t a[4], const uint32_t b[2]) {
    asm volatile("mma.sync.aligned.m16n8k16.row.col.f32.bf16.bf16.f32 "
                 "{%0,%1,%2,%3},{%4,%5,%6,%7},{%8,%9},{%0,%1,%2,%3};"
                 : "+f"(c[0]), "+f"(c[1]), "+f"(c[2]), "+f"(c[3])
                 : "r"(a[0]), "r"(a[1]), "r"(a[2]), "r"(a[3]), "r"(b[0]), "r"(b[1]));
}
__device__ __forceinline__ void hl_split(float x, unsigned short& h, unsigned short& l) {
    __nv_bfloat16 hb = __float2bfloat16_rn(x);
    float r = x - __bfloat162float(hb);
    __nv_bfloat16 lb = __float2bfloat16_rn(r);
    h = __bfloat16_as_ushort(hb);
    l = __bfloat16_as_ushort(lb);
}
__device__ __forceinline__ uint32_t pk(unsigned short lo, unsigned short hi) {
    return ((uint32_t)hi << 16) | lo;
}
// split 2 floats -> packed hi u32 and lo u32 (low half = first element)
__device__ __forceinline__ void split2(float x, float y, uint32_t& ph, uint32_t& pl) {
    unsigned short xh, xl, yh, yl;
    hl_split(x, xh, xl);
    hl_split(y, yh, yl);
    ph = pk(xh, yh);
    pl = pk(xl, yl);
}
__device__ __forceinline__ float dice_apply(float x, float m, float r, float a) {
    float p = fast_sigmoid((x - m) * r);
    return x * (a + p * (1.0f - a));
}

__global__ void __launch_bounds__(256, 2) din_pool_kernel(
    const float* __restrict__ q_emb,
    const float* __restrict__ k_emb,
    const int*   __restrict__ seqlen,
    const float* __restrict__ W1,
    const float* __restrict__ alpha1,
    const float* __restrict__ mean1,
    const float* __restrict__ var1,
    const float* __restrict__ W2,
    const float* __restrict__ alpha2,
    const float* __restrict__ mean2,
    const float* __restrict__ var2,
    const float* __restrict__ W3,
    float* __restrict__ out)
{
    extern __shared__ char smem_raw[];
    Smem& sm = *reinterpret_cast<Smem*>(smem_raw);

    const int tid  = threadIdx.x;
    const int lane = tid & 31;
    const int wid  = tid >> 5;
    const int b    = blockIdx.x;

    // ---- Stage weights/params (union .w phase) ----
    for (int i = tid; i < 64 * 64; i += 256) {
        int d = i >> 6, h = i & 63;
        sm.u.w.W1k[d][h]  = W1[(64 + d) * 64 + h] - W1[(128 + d) * 64 + h];
        sm.u.w.W1qk[d][h] = W1[(192 + d) * 64 + h];
    }
    for (int i = tid; i < 64 * 16; i += 256)
        sm.u.w.W2s[i >> 4][i & 15] = W2[i];
    if (tid < 16) {
        sm.W3s[tid] = W3[tid];
        sm.a2[tid]  = alpha2[tid];
        sm.m2[tid]  = mean2[tid];
        sm.r2[tid]  = rsqrtf(var2[tid] + EPSV);
    }
    if (tid < 64) {
        sm.Q[tid]  = q_emb[b * 64 + tid];
        sm.a1[tid] = alpha1[tid];
        sm.m1[tid] = mean1[tid];
        sm.r1[tid] = rsqrtf(var1[tid] + EPSV);
    }
    __syncthreads();

    // ---- Per-batch bias: q @ (W1[q] + W1[q-k]) ----
    if (tid < 64) {
        float acc = 0.0f;
        #pragma unroll 8
        for (int d = 0; d < 64; d++)
            acc = fmaf(sm.Q[d], W1[d * 64 + tid] + W1[(128 + d) * 64 + tid], acc);
        sm.Qbias[tid] = acc;
    }

    // ---- Extract B1 fragments (resident; warp owns n-strip 8*wid..8*wid+7) ----
    uint32_t b1hi[8][2], b1lo[8][2];
    {
        int n = 8 * wid + (lane >> 2);
        #pragma unroll
        for (int kt = 0; kt < 8; kt++) {
            int kb = kt * 16 + 2 * (lane & 3);
            const float* col0 = (kb < 64) ? &sm.u.w.W1k[kb][n] : &sm.u.w.W1qk[kb - 64][n];
            float w0 = col0[0];
            float w1 = col0[64];         // next k row (row stride 64 floats)
            float w8 = col0[8 * 64];
            float w9 = col0[9 * 64];
            split2(w0, w1, b1hi[kt][0], b1lo[kt][0]);
            split2(w8, w9, b1hi[kt][1], b1lo[kt][1]);
        }
    }
    // ---- Extract B2 fragments (warps 0,1 only) ----
    uint32_t b2hi[4][2], b2lo[4][2];
    if (wid < 2) {
        int n = 8 * wid + (lane >> 2);
        #pragma unroll
        for (int kt = 0; kt < 4; kt++) {
            int kb = kt * 16 + 2 * (lane & 3);
            float w0 = sm.u.w.W2s[kb][n];
            float w1 = sm.u.w.W2s[kb + 1][n];
            float w8 = sm.u.w.W2s[kb + 8][n];
            float w9 = sm.u.w.W2s[kb + 9][n];
            split2(w0, w1, b2hi[kt][0], b2lo[kt][0]);
            split2(w8, w9, b2hi[kt][1], b2lo[kt][1]);
        }
    }
    __syncthreads();   // staging region now reusable as A tiles; Qbias ready

    const int L = seqlen[b];

    // Hoisted per-thread constants
    const int n0 = 8 * wid + 2 * (lane & 3);        // stage-1 cols
    const float bia0 = sm.Qbias[n0], bia1 = sm.Qbias[n0 + 1];
    const float d1m0 = sm.m1[n0], d1r0 = sm.r1[n0], d1a0 = sm.a1[n0];
    const float d1m1 = sm.m1[n0 + 1], d1r1 = sm.r1[n0 + 1], d1a1 = sm.a1[n0 + 1];
    float d2m0 = 0.f, d2r0 = 0.f, d2a0 = 0.f, d2m1 = 0.f, d2r1 = 0.f, d2a1 = 0.f;
    float w3a = 0.f, w3b = 0.f;
    if (wid < 2) {
        int nn = 8 * wid + 2 * (lane & 3);
        d2m0 = sm.m2[nn];     d2r0 = sm.r2[nn];     d2a0 = sm.a2[nn];
        d2m1 = sm.m2[nn + 1]; d2r1 = sm.r2[nn + 1]; d2a1 = sm.a2[nn + 1];
        w3a  = sm.W3s[nn];    w3b  = sm.W3s[nn + 1];
    }

    const int ed = tid & 63;
    const int er = tid >> 6;
    float po = 0.0f;

    for (int s0 = 0; s0 < L; s0 += TS) {
        // ---- build K (fp32) + A (bf16 hi/lo) tiles ----
        #pragma unroll
        for (int it = 0; it < 4; it++) {
            int i  = tid + it * 256;
            int s  = i >> 4;
            int c4 = (i & 15) * 4;
            int gs = s0 + s;
            float4 kv = make_float4(0.f, 0.f, 0.f, 0.f);
            if (gs < SS)
                kv = *reinterpret_cast<const float4*>(&k_emb[((long)b * SS + gs) * 64 + c4]);
            *reinterpret_cast<float4*>(&sm.K[s][c4]) = kv;
            float4 q4 = *reinterpret_cast<const float4*>(&sm.Q[c4]);
            float4 kq = make_float4(kv.x * q4.x, kv.y * q4.y, kv.z * q4.z, kv.w * q4.w);
            uint32_t h0, l0, h1, l1;
            split2(kv.x, kv.y, h0, l0);
            split2(kv.z, kv.w, h1, l1);
            *reinterpret_cast<uint2*>(&sm.u.a.Ahi[s][c4]) = make_uint2(h0, h1);
            *reinterpret_cast<uint2*>(&sm.u.a.Alo[s][c4]) = make_uint2(l0, l1);
            split2(kq.x, kq.y, h0, l0);
            split2(kq.z, kq.w, h1, l1);
            *reinterpret_cast<uint2*>(&sm.u.a.Ahi[s][64 + c4]) = make_uint2(h0, h1);
            *reinterpret_cast<uint2*>(&sm.u.a.Alo[s][64 + c4]) = make_uint2(l0, l1);
        }
        __syncthreads();

        // ---- stage 1: C[64x8-strip] via mma ----
        float c1[4][4];
        #pragma unroll
        for (int mi = 0; mi < 4; mi++) {
            c1[mi][0] = bia0; c1[mi][1] = bia1;
            c1[mi][2] = bia0; c1[mi][3] = bia1;
        }
        const int arow = lane & 15;
        const int acol = (lane & 16) ? 8 : 0;
        #pragma unroll
        for (int kt = 0; kt < 8; kt++) {
            #pragma unroll
            for (int mi = 0; mi < 4; mi++) {
                uint32_t ah[4], al[4];
                ldsm4(ah, sptr(&sm.u.a.Ahi[mi * 16 + arow][kt * 16 + acol]));
                ldsm4(al, sptr(&sm.u.a.Alo[mi * 16 + arow][kt * 16 + acol]));
                mma16816(c1[mi], ah, b1hi[kt]);
                mma16816(c1[mi], al, b1hi[kt]);
                mma16816(c1[mi], ah, b1lo[kt]);
            }
        }
        // Dice1 + store H1 hi/lo
        #pragma unroll
        for (int mi = 0; mi < 4; mi++) {
            int r0 = mi * 16 + (lane >> 2);
            float x0 = dice_apply(c1[mi][0], d1m0, d1r0, d1a0);
            float x1 = dice_apply(c1[mi][1], d1m1, d1r1, d1a1);
            uint32_t ph, pl;
            split2(x0, x1, ph, pl);
            *reinterpret_cast<uint32_t*>(&sm.H1hi[r0][n0]) = ph;
            *reinterpret_cast<uint32_t*>(&sm.H1lo[r0][n0]) = pl;
            float x2 = dice_apply(c1[mi][2], d1m0, d1r0, d1a0);
            float x3 = dice_apply(c1[mi][3], d1m1, d1r1, d1a1);
            split2(x2, x3, ph, pl);
            *reinterpret_cast<uint32_t*>(&sm.H1hi[r0 + 8][n0]) = ph;
            *reinterpret_cast<uint32_t*>(&sm.H1lo[r0 + 8][n0]) = pl;
        }
        __syncthreads();

        // ---- stage 2 (warps 0,1): H2 = H1 @ W2, dice2, W3 dot ----
        if (wid < 2) {
            float c2[4][4];
            #pragma unroll
            for (int mi = 0; mi < 4; mi++)
                c2[mi][0] = c2[mi][1] = c2[mi][2] = c2[mi][3] = 0.f;
            #pragma unroll
            for (int kt = 0; kt < 4; kt++) {
                #pragma unroll
                for (int mi = 0; mi < 4; mi++) {
                    uint32_t ah[4], al[4];
                    ldsm4(ah, sptr(&sm.H1hi[mi * 16 + arow][kt * 16 + acol]));
                    ldsm4(al, sptr(&sm.H1lo[mi * 16 + arow][kt * 16 + acol]));
                    mma16816(c2[mi], ah, b2hi[kt]);
                    mma16816(c2[mi], al, b2hi[kt]);
                    mma16816(c2[mi], ah, b2lo[kt]);
                }
            }
            int slot = wid * 4 + (lane & 3);
            #pragma unroll
            for (int mi = 0; mi < 4; mi++) {
                int r0 = mi * 16 + (lane >> 2);
                float p0 = dice_apply(c2[mi][0], d2m0, d2r0, d2a0) * w3a
                         + dice_apply(c2[mi][1], d2m1, d2r1, d2a1) * w3b;
                sm.Spart[slot][r0] = p0;
                float p1 = dice_apply(c2[mi][2], d2m0, d2r0, d2a0) * w3a
                         + dice_apply(c2[mi][3], d2m1, d2r1, d2a1) * w3b;
                sm.Spart[slot][r0 + 8] = p1;
            }
        }
        __syncthreads();

        // ---- score + mask + sigmoid ----
        if (tid < TS) {
            float sc = 0.f;
            #pragma unroll
            for (int g = 0; g < 8; g++) sc += sm.Spart[g][tid];
            int gs = s0 + tid;
            sm.Score[tid] = (gs < L) ? fast_sigmoid(sc) : 0.0f;
        }
        __syncthreads();

        // ---- epilogue: out[ed] += sum_s score[s]*K[s][ed] ----
        #pragma unroll
        for (int i = 0; i < 16; i++) {
            int s = er * 16 + i;
            po = fmaf(sm.Score[s], sm.K[s][ed], po);
        }
        __syncthreads();
    }

    sm.Red[tid] = po;
    __syncthreads();
    if (tid < 64)
        out[b * 64 + tid] = sm.Red[tid] + sm.Red[64 + tid]
                          + sm.Red[128 + tid] + sm.Red[192 + tid];
}

extern "C" void kernel_launch(void* const* d_in, const int* in_sizes, int n_in,
                              void* d_out, int out_size) {
    const float* q      = (const float*)d_in[0];
    const float* k      = (const float*)d_in[1];
    const int*   sl     = (const int*)  d_in[2];
    const float* W1     = (const float*)d_in[3];
    const float* alpha1 = (const float*)d_in[4];
    const float* mean1  = (const float*)d_in[5];
    const float* var1   = (const float*)d_in[6];
    const float* W2     = (const float*)d_in[7];
    const float* alpha2 = (const float*)d_in[8];
    const float* mean2  = (const float*)d_in[9];
    const float* var2   = (const float*)d_in[10];
    const float* W3     = (const float*)d_in[11];
    float* out = (float*)d_out;

    cudaFuncSetAttribute(din_pool_kernel,
                         cudaFuncAttributeMaxDynamicSharedMemorySize,
                         (int)sizeof(Smem));
    din_pool_kernel<<<BB, 256, sizeof(Smem)>>>(
        q, k, sl, W1, alpha1, mean1, var1, W2, alpha2, mean2, var2, W3, out);
}

// round 4
// speedup vs baseline: 4.7974x; 1.0510x over previous
#include <cuda_runtime.h>
#include <cuda_bf16.h>
#include <cstdint>

#define BB 2048
#define SS 200
#define TS 64
#define EPSV 1e-9f
#define ASTRIDE 136   // bf16 row stride: 272B, granule stride 17 -> conflict-free ldmatrix
#define HSTRIDE 72    // bf16 row stride: 144B, granule stride 9  -> conflict-free ldmatrix

struct alignas(16) Smem {
    union {
        struct {   // init staging
            float W1k[64][64];    // W1[k-block] - W1[(q-k)-block]
            float W1qk[64][64];   // W1[q*k-block]
            float W2s[64][16];
        } w;
        struct {   // main loop: A = [k | k*q] in bf16 hi/lo
            __nv_bfloat16 Ahi[64][ASTRIDE];
            __nv_bfloat16 Alo[64][ASTRIDE];
        } a;
    } u;
    float Kraw[64][68];           // cp.async staging of next K tile (fp32)
    __nv_bfloat16 H1hi[64][HSTRIDE];
    __nv_bfloat16 H1lo[64][HSTRIDE];
    float Score[64];
    float2 Red2[256];
    float Q[64];
    float Qbias[64];
    float a1[64], m1[64], r1[64];
    float a2[16], m2[16], r2[16];
    float W3s[16];
};

__device__ __forceinline__ float fast_sigmoid(float x) {
    return __fdividef(1.0f, 1.0f + __expf(-x));
}
__device__ __forceinline__ uint32_t sptr(const void* p) {
    return (uint32_t)__cvta_generic_to_shared(p);
}
__device__ __forceinline__ void ldsm4(uint32_t r[4], uint32_t addr) {
    asm volatile("ldmatrix.sync.aligned.m8n8.x4.shared.b16 {%0,%1,%2,%3}, [%4];"
                 : "=r"(r[0]), "=r"(r[1]), "=r"(r[2]), "=r"(r[3]) : "r"(addr));
}
__device__ __forceinline__ void mma16816(float c[4], const uint32_t a[4], const uint32_t b[2]) {
    asm volatile("mma.sync.aligned.m16n8k16.row.col.f32.bf16.bf16.f32 "
                 "{%0,%1,%2,%3},{%4,%5,%6,%7},{%8,%9},{%0,%1,%2,%3};"
                 : "+f"(c[0]), "+f"(c[1]), "+f"(c[2]), "+f"(c[3])
                 : "r"(a[0]), "r"(a[1]), "r"(a[2]), "r"(a[3]), "r"(b[0]), "r"(b[1]));
}
__device__ __forceinline__ void hl_split(float x, unsigned short& h, unsigned short& l) {
    __nv_bfloat16 hb = __float2bfloat16_rn(x);
    float r = x - __bfloat162float(hb);
    __nv_bfloat16 lb = __float2bfloat16_rn(r);
    h = __bfloat16_as_ushort(hb);
    l = __bfloat16_as_ushort(lb);
}
__device__ __forceinline__ uint32_t pk(unsigned short lo, unsigned short hi) {
    return ((uint32_t)hi << 16) | lo;
}
__device__ __forceinline__ void split2(float x, float y, uint32_t& ph, uint32_t& pl) {
    unsigned short xh, xl, yh, yl;
    hl_split(x, xh, xl);
    hl_split(y, yh, yl);
    ph = pk(xh, yh);
    pl = pk(xl, yl);
}
__device__ __forceinline__ float dice_apply(float x, float m, float r, float a) {
    float p = fast_sigmoid((x - m) * r);
    return x * (a + p * (1.0f - a));
}

__global__ void __launch_bounds__(256, 2) din_pool_kernel(
    const float* __restrict__ q_emb,
    const float* __restrict__ k_emb,
    const int*   __restrict__ seqlen,
    const float* __restrict__ W1,
    const float* __restrict__ alpha1,
    const float* __restrict__ mean1,
    const float* __restrict__ var1,
    const float* __restrict__ W2,
    const float* __restrict__ alpha2,
    const float* __restrict__ mean2,
    const float* __restrict__ var2,
    const float* __restrict__ W3,
    float* __restrict__ out)
{
    extern __shared__ char smem_raw[];
    Smem& sm = *reinterpret_cast<Smem*>(smem_raw);

    const int tid  = threadIdx.x;
    const int lane = tid & 31;
    const int wid  = tid >> 5;
    const int b    = blockIdx.x;

    // ---- Stage weights/params (union .w phase) ----
    for (int i = tid; i < 64 * 64; i += 256) {
        int d = i >> 6, h = i & 63;
        sm.u.w.W1k[d][h]  = W1[(64 + d) * 64 + h] - W1[(128 + d) * 64 + h];
        sm.u.w.W1qk[d][h] = W1[(192 + d) * 64 + h];
    }
    for (int i = tid; i < 64 * 16; i += 256)
        sm.u.w.W2s[i >> 4][i & 15] = W2[i];
    if (tid < 16) {
        sm.W3s[tid] = W3[tid];
        sm.a2[tid]  = alpha2[tid];
        sm.m2[tid]  = mean2[tid];
        sm.r2[tid]  = rsqrtf(var2[tid] + EPSV);
    }
    if (tid < 64) {
        sm.Q[tid]  = q_emb[b * 64 + tid];
        sm.a1[tid] = alpha1[tid];
        sm.m1[tid] = mean1[tid];
        sm.r1[tid] = rsqrtf(var1[tid] + EPSV);
    }
    __syncthreads();

    // ---- Qbias partials over all 256 threads: q @ (W1[q] + W1[q-k]) ----
    {
        int h = tid & 63, g = tid >> 6;
        float acc = 0.0f;
        #pragma unroll
        for (int d = g * 16; d < g * 16 + 16; d++)
            acc = fmaf(sm.Q[d], W1[d * 64 + h] + W1[(128 + d) * 64 + h], acc);
        reinterpret_cast<float*>(sm.Red2)[tid] = acc;
    }

    // ---- B1 fragments (resident; warp owns n-strip 8*wid..8*wid+7) ----
    uint32_t b1hi[8][2], b1lo[8][2];
    {
        int n = 8 * wid + (lane >> 2);
        #pragma unroll
        for (int kt = 0; kt < 8; kt++) {
            int kb = kt * 16 + 2 * (lane & 3);
            const float* col0 = (kb < 64) ? &sm.u.w.W1k[kb][n] : &sm.u.w.W1qk[kb - 64][n];
            float w0 = col0[0];
            float w1 = col0[64];
            float w8 = col0[8 * 64];
            float w9 = col0[9 * 64];
            split2(w0, w1, b1hi[kt][0], b1lo[kt][0]);
            split2(w8, w9, b1hi[kt][1], b1lo[kt][1]);
        }
    }
    // ---- B2 fragments (warps 0..3; both n-tiles) ----
    uint32_t b2hi[4][2][2], b2lo[4][2][2];
    if (wid < 4) {
        int n = (lane >> 2);
        #pragma unroll
        for (int kt = 0; kt < 4; kt++) {
            int kb = kt * 16 + 2 * (lane & 3);
            #pragma unroll
            for (int ntile = 0; ntile < 2; ntile++) {
                int col = n + 8 * ntile;
                float w0 = sm.u.w.W2s[kb][col];
                float w1 = sm.u.w.W2s[kb + 1][col];
                float w8 = sm.u.w.W2s[kb + 8][col];
                float w9 = sm.u.w.W2s[kb + 9][col];
                split2(w0, w1, b2hi[kt][ntile][0], b2lo[kt][ntile][0]);
                split2(w8, w9, b2hi[kt][ntile][1], b2lo[kt][ntile][1]);
            }
        }
    }
    __syncthreads();   // staging read done; Qbias partials visible

    if (tid < 64) {
        const float* rp = reinterpret_cast<const float*>(sm.Red2);
        sm.Qbias[tid] = rp[tid] + rp[64 + tid] + rp[128 + tid] + rp[192 + tid];
    }
    __syncthreads();   // Qbias ready; union now free for A tiles

    const int L = seqlen[b];
    const int n_tiles = (L + TS - 1) >> 6;

    // Hoisted per-thread constants
    const int n0 = 8 * wid + 2 * (lane & 3);        // stage-1 cols
    const float bia0 = sm.Qbias[n0], bia1 = sm.Qbias[n0 + 1];
    const float d1m0 = sm.m1[n0], d1r0 = sm.r1[n0], d1a0 = sm.a1[n0];
    const float d1m1 = sm.m1[n0 + 1], d1r1 = sm.r1[n0 + 1], d1a1 = sm.a1[n0 + 1];

    const int eL = tid & 31;        // epilogue: 2 cols per thread
    const int er = tid >> 5;        // 8 row-groups of 8
    float2 po = make_float2(0.f, 0.f);

    const long kbase = (long)b * SS * 64;

    // ---- prefetch tile 0 ----
    {
        #pragma unroll
        for (int it = 0; it < 4; it++) {
            int i = tid + it * 256;
            int s = i >> 4, c4 = (i & 15) * 4;
            int gs = s;
            int gsc = (gs < SS) ? gs : 0;
            uint32_t dst = sptr(&sm.Kraw[s][c4]);
            const float* src = &k_emb[kbase + (long)gsc * 64 + c4];
            int szn = (gs < SS) ? 16 : 0;
            asm volatile("cp.async.ca.shared.global [%0], [%1], 16, %2;"
                         :: "r"(dst), "l"(src), "r"(szn));
        }
        asm volatile("cp.async.commit_group;");
    }

    for (int t = 0; t < n_tiles; t++) {
        const int s0 = t << 6;
        asm volatile("cp.async.wait_group 0;" ::: "memory");
        __syncthreads();   // Kraw ready everywhere; A free from prev epilogue

        // ---- build A (bf16 hi/lo) from Kraw ----
        #pragma unroll
        for (int it = 0; it < 4; it++) {
            int i  = tid + it * 256;
            int s  = i >> 4;
            int c4 = (i & 15) * 4;
            float4 kv = *reinterpret_cast<const float4*>(&sm.Kraw[s][c4]);
            float4 q4 = *reinterpret_cast<const float4*>(&sm.Q[c4]);
            float4 kq = make_float4(kv.x * q4.x, kv.y * q4.y, kv.z * q4.z, kv.w * q4.w);
            uint32_t h0, l0, h1, l1;
            split2(kv.x, kv.y, h0, l0);
            split2(kv.z, kv.w, h1, l1);
            *reinterpret_cast<uint2*>(&sm.u.a.Ahi[s][c4]) = make_uint2(h0, h1);
            *reinterpret_cast<uint2*>(&sm.u.a.Alo[s][c4]) = make_uint2(l0, l1);
            split2(kq.x, kq.y, h0, l0);
            split2(kq.z, kq.w, h1, l1);
            *reinterpret_cast<uint2*>(&sm.u.a.Ahi[s][64 + c4]) = make_uint2(h0, h1);
            *reinterpret_cast<uint2*>(&sm.u.a.Alo[s][64 + c4]) = make_uint2(l0, l1);
        }
        __syncthreads();   // A visible; Kraw free

        // ---- prefetch next tile (overlaps stage1/2/epilogue) ----
        if (s0 + TS < L) {
            #pragma unroll
            for (int it = 0; it < 4; it++) {
                int i = tid + it * 256;
                int s = i >> 4, c4 = (i & 15) * 4;
                int gs = s0 + TS + s;
                int gsc = (gs < SS) ? gs : 0;
                uint32_t dst = sptr(&sm.Kraw[s][c4]);
                const float* src = &k_emb[kbase + (long)gsc * 64 + c4];
                int szn = (gs < SS) ? 16 : 0;
                asm volatile("cp.async.ca.shared.global [%0], [%1], 16, %2;"
                             :: "r"(dst), "l"(src), "r"(szn));
            }
            asm volatile("cp.async.commit_group;");
        }

        // ---- stage 1: H1[64 x 8-strip] via mma ----
        float c1[4][4];
        #pragma unroll
        for (int mi = 0; mi < 4; mi++) {
            c1[mi][0] = bia0; c1[mi][1] = bia1;
            c1[mi][2] = bia0; c1[mi][3] = bia1;
        }
        const int arow = lane & 15;
        const int acol = (lane & 16) ? 8 : 0;
        #pragma unroll
        for (int kt = 0; kt < 8; kt++) {
            #pragma unroll
            for (int mi = 0; mi < 4; mi++) {
                uint32_t ah[4], al[4];
                ldsm4(ah, sptr(&sm.u.a.Ahi[mi * 16 + arow][kt * 16 + acol]));
                ldsm4(al, sptr(&sm.u.a.Alo[mi * 16 + arow][kt * 16 + acol]));
                mma16816(c1[mi], ah, b1hi[kt]);
                mma16816(c1[mi], al, b1hi[kt]);
                mma16816(c1[mi], ah, b1lo[kt]);
            }
        }
        // Dice1 + store H1 hi/lo
        #pragma unroll
        for (int mi = 0; mi < 4; mi++) {
            int r0 = mi * 16 + (lane >> 2);
            float x0 = dice_apply(c1[mi][0], d1m0, d1r0, d1a0);
            float x1 = dice_apply(c1[mi][1], d1m1, d1r1, d1a1);
            uint32_t ph, pl;
            split2(x0, x1, ph, pl);
            *reinterpret_cast<uint32_t*>(&sm.H1hi[r0][n0]) = ph;
            *reinterpret_cast<uint32_t*>(&sm.H1lo[r0][n0]) = pl;
            float x2 = dice_apply(c1[mi][2], d1m0, d1r0, d1a0);
            float x3 = dice_apply(c1[mi][3], d1m1, d1r1, d1a1);
            split2(x2, x3, ph, pl);
            *reinterpret_cast<uint32_t*>(&sm.H1hi[r0 + 8][n0]) = ph;
            *reinterpret_cast<uint32_t*>(&sm.H1lo[r0 + 8][n0]) = pl;
        }
        __syncthreads();

        // ---- stage 2 on warps 0..3 (mi = wid, all 16 cols) + fused score ----
        if (wid < 4) {
            float c2[2][4];
            c2[0][0]=c2[0][1]=c2[0][2]=c2[0][3]=0.f;
            c2[1][0]=c2[1][1]=c2[1][2]=c2[1][3]=0.f;
            #pragma unroll
            for (int kt = 0; kt < 4; kt++) {
                uint32_t ah[4], al[4];
                ldsm4(ah, sptr(&sm.H1hi[wid * 16 + arow][kt * 16 + acol]));
                ldsm4(al, sptr(&sm.H1lo[wid * 16 + arow][kt * 16 + acol]));
                #pragma unroll
                for (int ntile = 0; ntile < 2; ntile++) {
                    mma16816(c2[ntile], ah, b2hi[kt][ntile]);
                    mma16816(c2[ntile], al, b2hi[kt][ntile]);
                    mma16816(c2[ntile], ah, b2lo[kt][ntile]);
                }
            }
            // Dice2 + W3 dot (lane cols: 2(lane&3), +1, and +8)
            float pr0 = 0.f, pr1 = 0.f;
            #pragma unroll
            for (int ntile = 0; ntile < 2; ntile++) {
                int cc = 8 * ntile + 2 * (lane & 3);
                float m0 = sm.m2[cc],     rv0 = sm.r2[cc],     aa0 = sm.a2[cc],     w30 = sm.W3s[cc];
                float m1v = sm.m2[cc + 1], rv1 = sm.r2[cc + 1], aa1 = sm.a2[cc + 1], w31 = sm.W3s[cc + 1];
                pr0 += dice_apply(c2[ntile][0], m0, rv0, aa0) * w30
                     + dice_apply(c2[ntile][1], m1v, rv1, aa1) * w31;
                pr1 += dice_apply(c2[ntile][2], m0, rv0, aa0) * w30
                     + dice_apply(c2[ntile][3], m1v, rv1, aa1) * w31;
            }
            // quad reduce (across lane&3) -> full row score
            pr0 += __shfl_xor_sync(0xffffffffu, pr0, 1);
            pr0 += __shfl_xor_sync(0xffffffffu, pr0, 2);
            pr1 += __shfl_xor_sync(0xffffffffu, pr1, 1);
            pr1 += __shfl_xor_sync(0xffffffffu, pr1, 2);
            if ((lane & 3) == 0) {
                int r0 = wid * 16 + (lane >> 2);
                int gs0 = s0 + r0;
                sm.Score[r0]     = (gs0 < L)     ? fast_sigmoid(pr0) : 0.0f;
                sm.Score[r0 + 8] = (gs0 + 8 < L) ? fast_sigmoid(pr1) : 0.0f;
            }
        }
        __syncthreads();

        // ---- epilogue: po += score[s] * k[s][cols], k = Ahi + Alo ----
        #pragma unroll
        for (int i = 0; i < 8; i++) {
            int s = (er << 3) + i;
            float sc = sm.Score[s];
            __nv_bfloat162 hh = *reinterpret_cast<const __nv_bfloat162*>(&sm.u.a.Ahi[s][2 * eL]);
            __nv_bfloat162 ll = *reinterpret_cast<const __nv_bfloat162*>(&sm.u.a.Alo[s][2 * eL]);
            float2 hf = __bfloat1622float2(hh);
            float2 lf = __bfloat1622float2(ll);
            po.x = fmaf(sc, hf.x + lf.x, po.x);
            po.y = fmaf(sc, hf.y + lf.y, po.y);
        }
        // loop-top barrier protects A before next build
    }

    sm.Red2[tid] = po;
    __syncthreads();
    if (tid < 32) {
        float2 acc = sm.Red2[tid];
        #pragma unroll
        for (int g = 1; g < 8; g++) {
            float2 v = sm.Red2[g * 32 + tid];
            acc.x += v.x; acc.y += v.y;
        }
        out[b * 64 + 2 * tid]     = acc.x;
        out[b * 64 + 2 * tid + 1] = acc.y;
    }
}

extern "C" void kernel_launch(void* const* d_in, const int* in_sizes, int n_in,
                              void* d_out, int out_size) {
    const float* q      = (const float*)d_in[0];
    const float* k      = (const float*)d_in[1];
    const int*   sl     = (const int*)  d_in[2];
    const float* W1     = (const float*)d_in[3];
    const float* alpha1 = (const float*)d_in[4];
    const float* mean1  = (const float*)d_in[5];
    const float* var1   = (const float*)d_in[6];
    const float* W2     = (const float*)d_in[7];
    const float* alpha2 = (const float*)d_in[8];
    const float* mean2  = (const float*)d_in[9];
    const float* var2   = (const float*)d_in[10];
    const float* W3     = (const float*)d_in[11];
    float* out = (float*)d_out;

    cudaFuncSetAttribute(din_pool_kernel,
                         cudaFuncAttributeMaxDynamicSharedMemorySize,
                         (int)sizeof(Smem));
    din_pool_kernel<<<BB, 256, sizeof(Smem)>>>(
        q, k, sl, W1, alpha1, mean1, var1, W2, alpha2, mean2, var2, W3, out);
}

// round 5
// speedup vs baseline: 5.8565x; 1.2207x over previous
#include <cuda_runtime.h>
#include <cuda_bf16.h>
#include <cstdint>

#define BB 2048
#define SS 200
#define TS 64
#define EPSV 1e-9f
#define ASTRIDE 136   // bf16 row stride: 272B, granule stride 17 -> conflict-free ldmatrix
#define HSTRIDE 72    // bf16 row stride: 144B, granule stride 9  -> conflict-free ldmatrix
#define GRID 304      // 2 CTAs/SM, all resident

__device__ int g_ctr;

__global__ void reset_ctr_kernel() { g_ctr = GRID; }

struct alignas(16) Smem {
    union {
        struct {   // one-time staging
            float W1k[64][64];    // W1[k-block] - W1[(q-k)-block]
            float W1qk[64][64];   // W1[q*k-block]
            float W2s[64][16];
        } w;
        struct {   // main loop: A = [k | k*q] in bf16 hi/lo
            __nv_bfloat16 Ahi[64][ASTRIDE];
            __nv_bfloat16 Alo[64][ASTRIDE];
        } a;
    } u;
    float W1sum[64][65];          // W1[q-block] + W1[(q-k)-block] (persistent, for Qbias)
    float Kraw[64][68];           // cp.async staging of next K tile
    __nv_bfloat16 H1hi[64][HSTRIDE];
    __nv_bfloat16 H1lo[64][HSTRIDE];
    float Score[64];
    float2 Red2[256];
    float Q[64];
    float Qbias[64];
    float a1[64], m1[64], r1[64];
    float a2[16], m2[16], r2[16];
    float W3s[16];
    int Lslot, bnext;
};

__device__ __forceinline__ float fast_sigmoid(float x) {
    return __fdividef(1.0f, 1.0f + __expf(-x));
}
__device__ __forceinline__ uint32_t sptr(const void* p) {
    return (uint32_t)__cvta_generic_to_shared(p);
}
__device__ __forceinline__ void ldsm4(uint32_t r[4], uint32_t addr) {
    asm volatile("ldmatrix.sync.aligned.m8n8.x4.shared.b16 {%0,%1,%2,%3}, [%4];"
                 : "=r"(r[0]), "=r"(r[1]), "=r"(r[2]), "=r"(r[3]) : "r"(addr));
}
__device__ __forceinline__ void mma16816(float c[4], const uint32_t a[4], const uint32_t b[2]) {
    asm volatile("mma.sync.aligned.m16n8k16.row.col.f32.bf16.bf16.f32 "
                 "{%0,%1,%2,%3},{%4,%5,%6,%7},{%8,%9},{%0,%1,%2,%3};"
                 : "+f"(c[0]), "+f"(c[1]), "+f"(c[2]), "+f"(c[3])
                 : "r"(a[0]), "r"(a[1]), "r"(a[2]), "r"(a[3]), "r"(b[0]), "r"(b[1]));
}
__device__ __forceinline__ void hl_split(float x, unsigned short& h, unsigned short& l) {
    __nv_bfloat16 hb = __float2bfloat16_rn(x);
    float r = x - __bfloat162float(hb);
    __nv_bfloat16 lb = __float2bfloat16_rn(r);
    h = __bfloat16_as_ushort(hb);
    l = __bfloat16_as_ushort(lb);
}
__device__ __forceinline__ uint32_t pk(unsigned short lo, unsigned short hi) {
    return ((uint32_t)hi << 16) | lo;
}
__device__ __forceinline__ void split2(float x, float y, uint32_t& ph, uint32_t& pl) {
    unsigned short xh, xl, yh, yl;
    hl_split(x, xh, xl);
    hl_split(y, yh, yl);
    ph = pk(xh, yh);
    pl = pk(xl, yl);
}
__device__ __forceinline__ float dice_apply(float x, float m, float r, float a) {
    float p = fast_sigmoid((x - m) * r);
    return x * (a + p * (1.0f - a));
}

__global__ void __launch_bounds__(256, 2) din_pool_kernel(
    const float* __restrict__ q_emb,
    const float* __restrict__ k_emb,
    const int*   __restrict__ seqlen,
    const float* __restrict__ W1,
    const float* __restrict__ alpha1,
    const float* __restrict__ mean1,
    const float* __restrict__ var1,
    const float* __restrict__ W2,
    const float* __restrict__ alpha2,
    const float* __restrict__ mean2,
    const float* __restrict__ var2,
    const float* __restrict__ W3,
    float* __restrict__ out)
{
    extern __shared__ char smem_raw[];
    Smem& sm = *reinterpret_cast<Smem*>(smem_raw);

    const int tid  = threadIdx.x;
    const int lane = tid & 31;
    const int wid  = tid >> 5;

    // ================= one-time prologue =================
    for (int i = tid; i < 64 * 64; i += 256) {
        int d = i >> 6, h = i & 63;
        float wa = W1[d * 64 + h];
        float wb = W1[(64 + d) * 64 + h];
        float wc = W1[(128 + d) * 64 + h];
        float wd = W1[(192 + d) * 64 + h];
        sm.u.w.W1k[d][h]  = wb - wc;
        sm.u.w.W1qk[d][h] = wd;
        sm.W1sum[d][h]    = wa + wc;
    }
    for (int i = tid; i < 64 * 16; i += 256)
        sm.u.w.W2s[i >> 4][i & 15] = W2[i];
    if (tid < 16) {
        sm.W3s[tid] = W3[tid];
        sm.a2[tid]  = alpha2[tid];
        sm.m2[tid]  = mean2[tid];
        sm.r2[tid]  = rsqrtf(var2[tid] + EPSV);
    }
    if (tid < 64) {
        sm.a1[tid] = alpha1[tid];
        sm.m1[tid] = mean1[tid];
        sm.r1[tid] = rsqrtf(var1[tid] + EPSV);
    }
    __syncthreads();

    // B1 fragments (resident; warp owns n-strip 8*wid..8*wid+7)
    uint32_t b1hi[8][2], b1lo[8][2];
    {
        int n = 8 * wid + (lane >> 2);
        #pragma unroll
        for (int kt = 0; kt < 8; kt++) {
            int kb = kt * 16 + 2 * (lane & 3);
            const float* col0 = (kb < 64) ? &sm.u.w.W1k[kb][n] : &sm.u.w.W1qk[kb - 64][n];
            float w0 = col0[0];
            float w1 = col0[64];
            float w8 = col0[8 * 64];
            float w9 = col0[9 * 64];
            split2(w0, w1, b1hi[kt][0], b1lo[kt][0]);
            split2(w8, w9, b1hi[kt][1], b1lo[kt][1]);
        }
    }
    // B2 fragments (warps 0..3; both n-tiles)
    uint32_t b2hi[4][2][2], b2lo[4][2][2];
    if (wid < 4) {
        int n = (lane >> 2);
        #pragma unroll
        for (int kt = 0; kt < 4; kt++) {
            int kb = kt * 16 + 2 * (lane & 3);
            #pragma unroll
            for (int ntile = 0; ntile < 2; ntile++) {
                int col = n + 8 * ntile;
                float w0 = sm.u.w.W2s[kb][col];
                float w1 = sm.u.w.W2s[kb + 1][col];
                float w8 = sm.u.w.W2s[kb + 8][col];
                float w9 = sm.u.w.W2s[kb + 9][col];
                split2(w0, w1, b2hi[kt][ntile][0], b2lo[kt][ntile][0]);
                split2(w8, w9, b2hi[kt][ntile][1], b2lo[kt][ntile][1]);
            }
        }
    }
    __syncthreads();   // staging read complete; union free for A tiles

    // Batch-independent hoisted constants
    const int n0 = 8 * wid + 2 * (lane & 3);
    const float d1m0 = sm.m1[n0], d1r0 = sm.r1[n0], d1a0 = sm.a1[n0];
    const float d1m1 = sm.m1[n0 + 1], d1r1 = sm.r1[n0 + 1], d1a1 = sm.a1[n0 + 1];
    const int arow = lane & 15;
    const int acol = (lane & 16) ? 8 : 0;
    const int eL = tid & 31;
    const int er = tid >> 5;

    auto prefetch_tile = [&](int bb, int s0) {
        const long base = (long)bb * SS * 64;
        #pragma unroll
        for (int it = 0; it < 4; it++) {
            int i = tid + it * 256;
            int s = i >> 4, c4 = (i & 15) * 4;
            int gs = s0 + s;
            int gsc = (gs < SS) ? gs : 0;
            uint32_t dst = sptr(&sm.Kraw[s][c4]);
            const float* src = &k_emb[base + (long)gsc * 64 + c4];
            int szn = (gs < SS) ? 16 : 0;
            asm volatile("cp.async.ca.shared.global [%0], [%1], 16, %2;"
                         :: "r"(dst), "l"(src), "r"(szn));
        }
        asm volatile("cp.async.commit_group;");
    };

    // ================= persistent batch loop =================
    int b_cur = blockIdx.x;          // always < BB (GRID << BB)
    prefetch_tile(b_cur, 0);

    while (b_cur < BB) {
        // pop next work item; load per-batch data
        if (tid == 0) {
            sm.bnext = atomicAdd(&g_ctr, 1);
            sm.Lslot = seqlen[b_cur];
        }
        if (tid < 64) sm.Q[tid] = q_emb[b_cur * 64 + tid];
        __syncthreads();
        const int L = sm.Lslot;
        const int b_next = sm.bnext;
        const int n_tiles = (L + TS - 1) >> 6;

        // Qbias[h] = sum_d Q[d] * W1sum[d][h]   (threads 0..63)
        if (tid < 64) {
            float acc = 0.0f;
            #pragma unroll 8
            for (int d = 0; d < 64; d++)
                acc = fmaf(sm.Q[d], sm.W1sum[d][tid], acc);
            sm.Qbias[tid] = acc;
        }
        __syncthreads();
        const float bia0 = sm.Qbias[n0], bia1 = sm.Qbias[n0 + 1];

        float2 po = make_float2(0.f, 0.f);

        for (int t = 0; t < n_tiles; t++) {
            const int s0 = t << 6;
            asm volatile("cp.async.wait_group 0;" ::: "memory");
            __syncthreads();   // Kraw ready; A free

            // ---- build A (bf16 hi/lo) from Kraw ----
            #pragma unroll
            for (int it = 0; it < 4; it++) {
                int i  = tid + it * 256;
                int s  = i >> 4;
                int c4 = (i & 15) * 4;
                float4 kv = *reinterpret_cast<const float4*>(&sm.Kraw[s][c4]);
                float4 q4 = *reinterpret_cast<const float4*>(&sm.Q[c4]);
                float4 kq = make_float4(kv.x * q4.x, kv.y * q4.y, kv.z * q4.z, kv.w * q4.w);
                uint32_t h0, l0, h1, l1;
                split2(kv.x, kv.y, h0, l0);
                split2(kv.z, kv.w, h1, l1);
                *reinterpret_cast<uint2*>(&sm.u.a.Ahi[s][c4]) = make_uint2(h0, h1);
                *reinterpret_cast<uint2*>(&sm.u.a.Alo[s][c4]) = make_uint2(l0, l1);
                split2(kq.x, kq.y, h0, l0);
                split2(kq.z, kq.w, h1, l1);
                *reinterpret_cast<uint2*>(&sm.u.a.Ahi[s][64 + c4]) = make_uint2(h0, h1);
                *reinterpret_cast<uint2*>(&sm.u.a.Alo[s][64 + c4]) = make_uint2(l0, l1);
            }
            __syncthreads();   // A visible; Kraw free

            // ---- prefetch successor tile (this batch or next batch) ----
            if (t + 1 < n_tiles)           prefetch_tile(b_cur, s0 + TS);
            else if (b_next < BB)          prefetch_tile(b_next, 0);

            // ---- stage 1: H1[64 x 8-strip] via mma ----
            float c1[4][4];
            #pragma unroll
            for (int mi = 0; mi < 4; mi++) {
                c1[mi][0] = bia0; c1[mi][1] = bia1;
                c1[mi][2] = bia0; c1[mi][3] = bia1;
            }
            #pragma unroll
            for (int kt = 0; kt < 8; kt++) {
                #pragma unroll
                for (int mi = 0; mi < 4; mi++) {
                    uint32_t ah[4], al[4];
                    ldsm4(ah, sptr(&sm.u.a.Ahi[mi * 16 + arow][kt * 16 + acol]));
                    ldsm4(al, sptr(&sm.u.a.Alo[mi * 16 + arow][kt * 16 + acol]));
                    mma16816(c1[mi], ah, b1hi[kt]);
                    mma16816(c1[mi], al, b1hi[kt]);
                    mma16816(c1[mi], ah, b1lo[kt]);
                }
            }
            // Dice1 + store H1 hi/lo
            #pragma unroll
            for (int mi = 0; mi < 4; mi++) {
                int r0 = mi * 16 + (lane >> 2);
                float x0 = dice_apply(c1[mi][0], d1m0, d1r0, d1a0);
                float x1 = dice_apply(c1[mi][1], d1m1, d1r1, d1a1);
                uint32_t ph, pl;
                split2(x0, x1, ph, pl);
                *reinterpret_cast<uint32_t*>(&sm.H1hi[r0][n0]) = ph;
                *reinterpret_cast<uint32_t*>(&sm.H1lo[r0][n0]) = pl;
                float x2 = dice_apply(c1[mi][2], d1m0, d1r0, d1a0);
                float x3 = dice_apply(c1[mi][3], d1m1, d1r1, d1a1);
                split2(x2, x3, ph, pl);
                *reinterpret_cast<uint32_t*>(&sm.H1hi[r0 + 8][n0]) = ph;
                *reinterpret_cast<uint32_t*>(&sm.H1lo[r0 + 8][n0]) = pl;
            }
            __syncthreads();

            // ---- stage 2 (warps 0..3) + fused score ----
            if (wid < 4) {
                float c2[2][4];
                c2[0][0]=c2[0][1]=c2[0][2]=c2[0][3]=0.f;
                c2[1][0]=c2[1][1]=c2[1][2]=c2[1][3]=0.f;
                #pragma unroll
                for (int kt = 0; kt < 4; kt++) {
                    uint32_t ah[4], al[4];
                    ldsm4(ah, sptr(&sm.H1hi[wid * 16 + arow][kt * 16 + acol]));
                    ldsm4(al, sptr(&sm.H1lo[wid * 16 + arow][kt * 16 + acol]));
                    #pragma unroll
                    for (int ntile = 0; ntile < 2; ntile++) {
                        mma16816(c2[ntile], ah, b2hi[kt][ntile]);
                        mma16816(c2[ntile], al, b2hi[kt][ntile]);
                        mma16816(c2[ntile], ah, b2lo[kt][ntile]);
                    }
                }
                float pr0 = 0.f, pr1 = 0.f;
                #pragma unroll
                for (int ntile = 0; ntile < 2; ntile++) {
                    int cc = 8 * ntile + 2 * (lane & 3);
                    float m0 = sm.m2[cc],     rv0 = sm.r2[cc],     aa0 = sm.a2[cc],     w30 = sm.W3s[cc];
                    float m1v = sm.m2[cc + 1], rv1 = sm.r2[cc + 1], aa1 = sm.a2[cc + 1], w31 = sm.W3s[cc + 1];
                    pr0 += dice_apply(c2[ntile][0], m0, rv0, aa0) * w30
                         + dice_apply(c2[ntile][1], m1v, rv1, aa1) * w31;
                    pr1 += dice_apply(c2[ntile][2], m0, rv0, aa0) * w30
                         + dice_apply(c2[ntile][3], m1v, rv1, aa1) * w31;
                }
                pr0 += __shfl_xor_sync(0xffffffffu, pr0, 1);
                pr0 += __shfl_xor_sync(0xffffffffu, pr0, 2);
                pr1 += __shfl_xor_sync(0xffffffffu, pr1, 1);
                pr1 += __shfl_xor_sync(0xffffffffu, pr1, 2);
                if ((lane & 3) == 0) {
                    int r0 = wid * 16 + (lane >> 2);
                    int gs0 = s0 + r0;
                    sm.Score[r0]     = (gs0 < L)     ? fast_sigmoid(pr0) : 0.0f;
                    sm.Score[r0 + 8] = (gs0 + 8 < L) ? fast_sigmoid(pr1) : 0.0f;
                }
            }
            __syncthreads();

            // ---- epilogue: po += score[s] * k[s][cols], k = Ahi + Alo ----
            #pragma unroll
            for (int i = 0; i < 8; i++) {
                int s = (er << 3) + i;
                float sc = sm.Score[s];
                __nv_bfloat162 hh = *reinterpret_cast<const __nv_bfloat162*>(&sm.u.a.Ahi[s][2 * eL]);
                __nv_bfloat162 ll = *reinterpret_cast<const __nv_bfloat162*>(&sm.u.a.Alo[s][2 * eL]);
                float2 hf = __bfloat1622float2(hh);
                float2 lf = __bfloat1622float2(ll);
                po.x = fmaf(sc, hf.x + lf.x, po.x);
                po.y = fmaf(sc, hf.y + lf.y, po.y);
            }
            // loop-top barrier protects A before next build
        }

        // ---- output for this batch row ----
        sm.Red2[tid] = po;
        __syncthreads();
        if (tid < 32) {
            float2 acc = sm.Red2[tid];
            #pragma unroll
            for (int g = 1; g < 8; g++) {
                float2 v = sm.Red2[g * 32 + tid];
                acc.x += v.x; acc.y += v.y;
            }
            out[b_cur * 64 + 2 * tid]     = acc.x;
            out[b_cur * 64 + 2 * tid + 1] = acc.y;
        }
        b_cur = b_next;
    }
}

extern "C" void kernel_launch(void* const* d_in, const int* in_sizes, int n_in,
                              void* d_out, int out_size) {
    const float* q      = (const float*)d_in[0];
    const float* k      = (const float*)d_in[1];
    const int*   sl     = (const int*)  d_in[2];
    const float* W1     = (const float*)d_in[3];
    const float* alpha1 = (const float*)d_in[4];
    const float* mean1  = (const float*)d_in[5];
    const float* var1   = (const float*)d_in[6];
    const float* W2     = (const float*)d_in[7];
    const float* alpha2 = (const float*)d_in[8];
    const float* mean2  = (const float*)d_in[9];
    const float* var2   = (const float*)d_in[10];
    const float* W3     = (const float*)d_in[11];
    float* out = (float*)d_out;

    reset_ctr_kernel<<<1, 1>>>();
    cudaFuncSetAttribute(din_pool_kernel,
                         cudaFuncAttributeMaxDynamicSharedMemorySize,
                         (int)sizeof(Smem));
    din_pool_kernel<<<GRID, 256, sizeof(Smem)>>>(
        q, k, sl, W1, alpha1, mean1, var1, W2, alpha2, mean2, var2, W3, out);
}